// round 1
// baseline (speedup 1.0000x reference)
#include <cuda_runtime.h>

#define BB 4096
#define SS 200
#define DD 64
#define NOUT 18
#define NTHREADS 320
#define CHUNK 100

__device__ float g_loss_part[BB];

__global__ __launch_bounds__(NTHREADS, 3) void tan_kernel(
    const int* __restrict__ x, const float* __restrict__ y,
    const float* __restrict__ emb, const float* __restrict__ attw,
    const float* __restrict__ attb,
    const float* __restrict__ W0, const float* __restrict__ W1,
    const float* __restrict__ W2, const float* __restrict__ W3,
    const float* __restrict__ W4,
    float* __restrict__ out, int S_total)
{
    __shared__ float s_emb[CHUNK * DD];      // 25600 B
    __shared__ float s_p[CHUNK * 8];         // 3200 B  (raw u, then exp(tanh(u+b)))
    __shared__ int   s_x[SS];                // 800 B
    __shared__ float s_urep[5 * DD];         // 1280 B (raw numerators)
    __shared__ float s_comb[10 * 5 * 32 * 2];// 12800 B (per-warp partials)
    __shared__ float s_dcomb[10 * 5];        // 200 B
    __shared__ float s_deninv[5];
    __shared__ float s_wu[NOUT];
    __shared__ float s_lossi[5];

    const int b    = blockIdx.x;
    const int t    = threadIdx.x;
    const int lane = t & 31;
    const int warp = t >> 5;
    const int q    = t & 15;          // quad index within a 64-float row

    // stage x row
    for (int i = t; i < SS; i += NTHREADS) s_x[i] = x[b * SS + i];

    // stage attention weights for this thread's quad: aw[k][j] = attw[k*64 + q*4 + j]
    float aw[5][4];
#pragma unroll
    for (int k = 0; k < 5; ++k) {
        float4 v = *(const float4*)&attw[k * DD + q * 4];
        aw[k][0] = v.x; aw[k][1] = v.y; aw[k][2] = v.z; aw[k][3] = v.w;
    }
    __syncthreads();

    // accumulators: numerator pairs per (k, d2=lane) and denominators
    float ax[5], ay[5], dsum[5];
#pragma unroll
    for (int k = 0; k < 5; ++k) { ax[k] = 0.f; ay[k] = 0.f; dsum[k] = 0.f; }

    for (int ch = 0; ch < 2; ++ch) {
        // ---- phase 1: gather rows + attention partial dots + shuffle reduce ----
#pragma unroll
        for (int it = 0; it < 5; ++it) {
            int sl  = it * 20 + (t >> 4);              // 0..99 local row
            int row = s_x[ch * CHUNK + sl];
            float4 e = __ldg((const float4*)&emb[row * DD + q * 4]);
            *(float4*)&s_emb[sl * DD + q * 4] = e;
            float part[5];
#pragma unroll
            for (int k = 0; k < 5; ++k)
                part[k] = e.x * aw[k][0] + e.y * aw[k][1] + e.z * aw[k][2] + e.w * aw[k][3];
#pragma unroll
            for (int m = 8; m >= 1; m >>= 1) {
#pragma unroll
                for (int k = 0; k < 5; ++k)
                    part[k] += __shfl_xor_sync(0xffffffffu, part[k], m, 16);
            }
            if (q == 0) {
#pragma unroll
                for (int k = 0; k < 5; ++k) s_p[sl * 8 + k] = part[k];
            }
        }
        __syncthreads();

        // ---- phase 2: tanh + exp (dense, no max-subtraction needed: |tanh|<=1) ----
        if (t < CHUNK) {
#pragma unroll
            for (int k = 0; k < 5; ++k) {
                float u  = s_p[t * 8 + k] + __ldg(&attb[k]);
                float a  = __expf(2.0f * u);
                float th = 1.0f - 2.0f / (a + 1.0f);   // tanh(u)
                s_p[t * 8 + k] = __expf(th);
            }
        }
        __syncthreads();

        // ---- phase 3: accumulate softmax numerators + denominators ----
        // warp handles 10 rows, lane = d-pair index
        {
            const int base = warp * 10;
#pragma unroll
            for (int si = 0; si < 10; ++si) {
                int sl = base + si;
                float4 pv = *(const float4*)&s_p[sl * 8];
                float  p4 = s_p[sl * 8 + 4];
                float2 e  = *(const float2*)&s_emb[sl * DD + lane * 2];
                ax[0] += pv.x * e.x; ay[0] += pv.x * e.y;
                ax[1] += pv.y * e.x; ay[1] += pv.y * e.y;
                ax[2] += pv.z * e.x; ay[2] += pv.z * e.y;
                ax[3] += pv.w * e.x; ay[3] += pv.w * e.y;
                ax[4] += p4   * e.x; ay[4] += p4   * e.y;
                dsum[0] += pv.x; dsum[1] += pv.y; dsum[2] += pv.z;
                dsum[3] += pv.w; dsum[4] += p4;
            }
        }
        __syncthreads();
    }

    // ---- combine per-warp partials ----
#pragma unroll
    for (int k = 0; k < 5; ++k) {
        int idx = ((warp * 5 + k) * 32 + lane) * 2;
        s_comb[idx]     = ax[k];
        s_comb[idx + 1] = ay[k];
    }
    if (lane == 0) {
#pragma unroll
        for (int k = 0; k < 5; ++k) s_dcomb[warp * 5 + k] = dsum[k];
    }
    __syncthreads();

    if (t < 5) {
        float dn = 0.f;
#pragma unroll
        for (int w = 0; w < 10; ++w) dn += s_dcomb[w * 5 + t];
        s_deninv[t] = 1.0f / dn;
    }
    if (t < 160) {
        int k = t >> 5, d2 = t & 31;
        float sx = 0.f, sy = 0.f;
#pragma unroll
        for (int w = 0; w < 10; ++w) {
            float2 v = *(const float2*)&s_comb[((w * 5 + k) * 32 + d2) * 2];
            sx += v.x; sy += v.y;
        }
        s_urep[k * DD + d2 * 2]     = sx;   // raw numerator; scaled by deninv later
        s_urep[k * DD + d2 * 2 + 1] = sy;
    }
    __syncthreads();

    // ---- phase 5: W_user = user_rep @ Wi^T  (warp per output, shuffle reduce) ----
    for (int j = warp; j < NOUT; j += 10) {
        int i = (j < 2) ? 0 : (j < 6) ? 1 : (j < 10) ? 2 : (j < 12) ? 3 : 4;
        int base = (i == 0) ? 0 : (i == 1) ? 2 : (i == 2) ? 6 : (i == 3) ? 10 : 12;
        int r = j - base;
        const float* w = (i == 0) ? W0 : (i == 1) ? W1 : (i == 2) ? W2 : (i == 3) ? W3 : W4;
        float v = s_urep[i * DD + lane]      * __ldg(&w[r * DD + lane])
                + s_urep[i * DD + 32 + lane] * __ldg(&w[r * DD + 32 + lane]);
#pragma unroll
        for (int m = 16; m >= 1; m >>= 1) v += __shfl_xor_sync(0xffffffffu, v, m);
        if (lane == 0) s_wu[j] = v * s_deninv[i];
    }
    __syncthreads();

    // ---- phase 6: per-group softmax, logits + cross-entropy ----
    if (t < 5) {
        int c0 = (t == 0) ? 0 : (t == 1) ? 2 : (t == 2) ? 6 : (t == 3) ? 10 : 12;
        int n  = (t == 0) ? 2 : (t == 1) ? 4 : (t == 2) ? 4 : (t == 3) ? 2 : 6;
        float m = -1e30f;
#pragma unroll 6
        for (int j = 0; j < 6; ++j) if (j < n) m = fmaxf(m, s_wu[c0 + j]);
        float ex[6], sum = 0.f;
#pragma unroll 6
        for (int j = 0; j < 6; ++j) {
            ex[j] = (j < n) ? __expf(s_wu[c0 + j] - m) : 0.f;
            sum += ex[j];
        }
        float inv = 1.0f / sum;
        float lse = __logf(sum);
        float li = 0.f;
#pragma unroll 6
        for (int j = 0; j < 6; ++j) {
            if (j < n) {
                out[b * NOUT + c0 + j] = ex[j] * inv;
                float logp = s_wu[c0 + j] - m - lse;
                li -= logp * __ldg(&y[b * NOUT + c0 + j]);
            }
        }
        s_lossi[t] = li;
    }
    __syncthreads();
    if (t == 0)
        g_loss_part[b] = s_lossi[0] + s_lossi[1] + s_lossi[2] + s_lossi[3] + s_lossi[4];
}

// Deterministic tree reduction of per-batch loss partials.
__global__ void loss_reduce_kernel(float* __restrict__ out, int out_size)
{
    __shared__ float sm[1024];
    int t = threadIdx.x;
    float v = g_loss_part[t] + g_loss_part[t + 1024] +
              g_loss_part[t + 2048] + g_loss_part[t + 3072];
    sm[t] = v;
    __syncthreads();
    for (int s = 512; s > 0; s >>= 1) {
        if (t < s) sm[t] += sm[t + s];
        __syncthreads();
    }
    if (t == 0) out[out_size - 1] = sm[0] * (1.0f / (float)BB);
}

extern "C" void kernel_launch(void* const* d_in, const int* in_sizes, int n_in,
                              void* d_out, int out_size)
{
    const int*   x    = (const int*)d_in[0];
    const float* y    = (const float*)d_in[1];
    const float* emb  = (const float*)d_in[2];
    const float* attw = (const float*)d_in[3];
    const float* attb = (const float*)d_in[4];
    const float* W0   = (const float*)d_in[5];
    const float* W1   = (const float*)d_in[6];
    const float* W2   = (const float*)d_in[7];
    const float* W3   = (const float*)d_in[8];
    const float* W4   = (const float*)d_in[9];
    float* out = (float*)d_out;

    int B = in_sizes[0] / SS;   // 4096

    tan_kernel<<<B, NTHREADS>>>(x, y, emb, attw, attb, W0, W1, W2, W3, W4, out, SS);
    loss_reduce_kernel<<<1, 1024>>>(out, out_size);
}